// round 6
// baseline (speedup 1.0000x reference)
#include <cuda_runtime.h>
#include <cuda_fp16.h>
#include <cstdint>
#include <cstddef>

// ---- problem shapes ----
#define MM 8192
#define NN 11008
#define KK 4096
#define GG 32

// ---- tiling ----
#define BM 128
#define BN 256
#define BK 32
#define KT (KK / BK)            // 128
#define THREADS 256
#define NB (NN / BN)            // 43
#define MB (MM / BM)            // 64

// per-stage smem: A 16 tiles x 512B = 8 KB, B 64 tiles x 256B = 16 KB
#define A_STAGE_BYTES 8192
#define STAGE_BYTES   24576
#define SMEM_TOTAL    (2 * STAGE_BYTES)   // 49152

// ---------------- helpers ----------------
__device__ __forceinline__ uint32_t smem_u32(const void* p) {
    uint32_t a;
    asm("{ .reg .u64 t; cvta.to.shared.u64 t, %1; cvt.u32.u64 %0, t; }"
        : "=r"(a) : "l"(p));
    return a;
}
__device__ __forceinline__ void mma_f16(float* c, const uint32_t* a, const uint32_t* b) {
    asm volatile(
        "mma.sync.aligned.m16n8k16.row.col.f32.f16.f16.f32 "
        "{%0,%1,%2,%3}, {%4,%5,%6,%7}, {%8,%9}, {%0,%1,%2,%3};\n"
        : "+f"(c[0]), "+f"(c[1]), "+f"(c[2]), "+f"(c[3])
        : "r"(a[0]), "r"(a[1]), "r"(a[2]), "r"(a[3]),
          "r"(b[0]), "r"(b[1]));
}
__device__ __forceinline__ uint32_t pack2(float x, float y) {
    __half2 h = __floats2half2_rn(x, y);
    return *reinterpret_cast<uint32_t*>(&h);
}

// ---------------- fused GEMM ----------------
// Fragment layout per stage (identical to R4 scratch layout):
//   A tile (kt2*8 + mt), 16x16, lane holds uint4 {a00,a10,a01,a11} at tile*512 + lane*16
//   B tile (kt2*32 + nt), 8x16,  lane holds uint2 {b0,b1}          at 8192 + tile*256 + lane*8
// Conversion ownership: warp w -> A tiles mt=w (kt2=0,1); B tiles nt=4w..4w+3 (kt2=0,1).
__global__ __launch_bounds__(THREADS, 1)
void gemm_fused(const float* __restrict__ X, const float* __restrict__ SX,
                const float* __restrict__ W, const float* __restrict__ WS,
                const float* __restrict__ OFF, float* __restrict__ OUT) {
    extern __shared__ char smem[];
    const uint32_t sbase = smem_u32(smem);

    const int tid = threadIdx.x;
    const int wid = tid >> 5;
    const int lane = tid & 31;
    const int lq  = lane >> 2;        // 0..7
    const int lr2 = (lane & 3) * 2;   // 0,2,4,6
    const int wm = wid >> 2;          // 0..1
    const int wn = wid & 3;           // 0..3

    // CTA swizzle: groups of 8 mb per nb sweep (L2 reuse of X within a wave).
    const int bid = blockIdx.x;
    const int grp = bid / (8 * NB);
    const int rem = bid - grp * (8 * NB);
    const int mb = grp * 8 + (rem & 7);
    const int nb = rem >> 3;

    // ---- conversion-side addressing ----
    const int arow = mb * BM + wid * 16 + lq;           // A row (and +8)
    const float* Xr0 = X + (size_t)arow * KK;
    const float* Xr1 = Xr0 + (size_t)8 * KK;
    const float s0 = __ldg(SX + arow);
    const float s1 = __ldg(SX + arow + 8);

    const int nrow = nb * BN + wid * 32 + lq;           // B row base (nt=4w), +8 per tile
    const float* Wn   = W   + (size_t)nrow * KK;
    const float* WSn  = WS  + (size_t)nrow * GG;
    const float* OFFn = OFF + (size_t)nrow * GG;

    float ws4[4], of4[4];
    auto refresh = [&](int g) {
        #pragma unroll
        for (int i = 0; i < 4; i++) {
            ws4[i] = __ldg(WSn  + (size_t)i * 8 * GG + g);
            of4[i] = __ldg(OFFn + (size_t)i * 8 * GG + g);
        }
    };

    // staging registers
    float2 a_st[2][4];
    float2 b_st[2][4][2];

    auto ldg_tile = [&](int kt) {
        #pragma unroll
        for (int kt2 = 0; kt2 < 2; kt2++) {
            const int c = kt * BK + kt2 * 16 + lr2;
            a_st[kt2][0] = *reinterpret_cast<const float2*>(Xr0 + c);
            a_st[kt2][1] = *reinterpret_cast<const float2*>(Xr1 + c);
            a_st[kt2][2] = *reinterpret_cast<const float2*>(Xr0 + c + 8);
            a_st[kt2][3] = *reinterpret_cast<const float2*>(Xr1 + c + 8);
            #pragma unroll
            for (int i = 0; i < 4; i++) {
                const float* w = Wn + (size_t)i * 8 * KK + c;
                b_st[kt2][i][0] = *reinterpret_cast<const float2*>(w);
                b_st[kt2][i][1] = *reinterpret_cast<const float2*>(w + 8);
            }
        }
    };

    auto cvt_sts = [&](int s) {
        const uint32_t sa = sbase + s * STAGE_BYTES;
        #pragma unroll
        for (int kt2 = 0; kt2 < 2; kt2++) {
            uint4 va;
            va.x = pack2(a_st[kt2][0].x * s0, a_st[kt2][0].y * s0);
            va.y = pack2(a_st[kt2][1].x * s1, a_st[kt2][1].y * s1);
            va.z = pack2(a_st[kt2][2].x * s0, a_st[kt2][2].y * s0);
            va.w = pack2(a_st[kt2][3].x * s1, a_st[kt2][3].y * s1);
            *reinterpret_cast<uint4*>(smem + s * STAGE_BYTES
                                      + (kt2 * 8 + wid) * 512 + lane * 16) = va;
            #pragma unroll
            for (int i = 0; i < 4; i++) {
                const float ws = ws4[i], of = of4[i];
                uint2 vb;
                vb.x = pack2((b_st[kt2][i][0].x - of) * ws,
                             (b_st[kt2][i][0].y - of) * ws);
                vb.y = pack2((b_st[kt2][i][1].x - of) * ws,
                             (b_st[kt2][i][1].y - of) * ws);
                *reinterpret_cast<uint2*>(smem + s * STAGE_BYTES + A_STAGE_BYTES
                                          + (kt2 * 32 + wid * 4 + i) * 256 + lane * 8) = vb;
            }
        }
        (void)sa;
    };

    // ---- accumulators ----
    float acc[4][8][4];
    #pragma unroll
    for (int i = 0; i < 4; i++)
        #pragma unroll
        for (int j = 0; j < 8; j++)
            #pragma unroll
            for (int c = 0; c < 4; c++) acc[i][j][c] = 0.f;

    auto compute = [&](int s) {
        const char* As = smem + s * STAGE_BYTES;
        const char* Bs = As + A_STAGE_BYTES;
        #pragma unroll
        for (int kt2 = 0; kt2 < 2; kt2++) {
            uint4 af[4];
            #pragma unroll
            for (int mi = 0; mi < 4; mi++) {
                const int mt = wm * 4 + mi;
                af[mi] = *reinterpret_cast<const uint4*>(
                    As + (kt2 * 8 + mt) * 512 + lane * 16);
            }
            uint2 bf[8];
            #pragma unroll
            for (int ni = 0; ni < 8; ni++) {
                const int nt = wn * 8 + ni;
                bf[ni] = *reinterpret_cast<const uint2*>(
                    Bs + (kt2 * 32 + nt) * 256 + lane * 8);
            }
            #pragma unroll
            for (int mi = 0; mi < 4; mi++)
                #pragma unroll
                for (int ni = 0; ni < 8; ni++)
                    mma_f16(acc[mi][ni],
                            reinterpret_cast<const uint32_t*>(&af[mi]),
                            reinterpret_cast<const uint32_t*>(&bf[ni]));
        }
    };

    // ---- pipeline: reg-staged double buffer ----
    refresh(0);
    ldg_tile(0);
    cvt_sts(0);
    __syncthreads();

    #pragma unroll 1
    for (int kt = 0; kt < KT; kt++) {
        if (kt + 1 < KT) {
            if (((kt + 1) & 3) == 0) refresh((kt + 1) >> 2);
            ldg_tile(kt + 1);                 // LDG early; latency hidden by compute
        }
        compute(kt & 1);
        if (kt + 1 < KT) {
            cvt_sts((kt + 1) & 1);
            __syncthreads();
        }
    }

    // ---- epilogue ----
    const int m0 = mb * BM + wm * 64;
    const int n0 = nb * BN + wn * 64;
    #pragma unroll
    for (int mi = 0; mi < 4; mi++) {
        const int row = m0 + mi * 16 + lq;
        #pragma unroll
        for (int ni = 0; ni < 8; ni++) {
            const int col = n0 + ni * 8 + (lane & 3) * 2;
            float2 v0, v1;
            v0.x = acc[mi][ni][0]; v0.y = acc[mi][ni][1];
            v1.x = acc[mi][ni][2]; v1.y = acc[mi][ni][3];
            *reinterpret_cast<float2*>(OUT + (size_t)row * NN + col)       = v0;
            *reinterpret_cast<float2*>(OUT + (size_t)(row + 8) * NN + col) = v1;
        }
    }
}

// ---------------- launch ----------------
extern "C" void kernel_launch(void* const* d_in, const int* in_sizes, int n_in,
                              void* d_out, int out_size) {
    const float* X   = (const float*)d_in[0];
    const float* SX  = (const float*)d_in[1];
    const float* W   = (const float*)d_in[2];
    const float* WS  = (const float*)d_in[3];
    const float* OFF = (const float*)d_in[4];
    float* OUT = (float*)d_out;

    cudaFuncSetAttribute(gemm_fused,
                         cudaFuncAttributeMaxDynamicSharedMemorySize, SMEM_TOTAL);

    gemm_fused<<<MB * NB, THREADS, SMEM_TOTAL>>>(X, SX, W, WS, OFF, OUT);
}

// round 7
// speedup vs baseline: 1.0972x; 1.0972x over previous
#include <cuda_runtime.h>
#include <cuda_fp16.h>
#include <cstdint>
#include <cstddef>

// ---- problem shapes ----
#define MM 8192
#define NN 11008
#define KK 4096
#define GG 32

// ---- GEMM tiling ----
#define BM 128
#define BN 256
#define BK 32
#define STAGES 4
#define KT (KK / BK)               // 128
#define THREADS 256

#define NB (NN / BN)               // 43
#define MB (MM / BM)               // 64

// packed A (fp16): per (mb,kt): kt2(2) x mt(8) tiles of 16x16, 256 halves each
#define A_HALVES 4096              // per (mb,kt)  -> 8 KB
#define A_BYTES  (A_HALVES * 2)
// packed B (fp16): per (nb,kt): kt2(2) x nt(32) tiles of 8x16, 128 halves each
#define B_HALVES 8192              // per (nb,kt)  -> 16 KB
#define B_BYTES  (B_HALVES * 2)

#define STAGE_BYTES (A_BYTES + B_BYTES)         // 24576
#define SMEM_TOTAL  (STAGES * STAGE_BYTES)      // 98304

#define XTILES (MB * KT * 2 * 8)   // 131072 warp-tiles for X
#define WTILES (NB * KT * 2 * 32)  // 352256 warp-tiles for W

// ---- scratch ----
__device__ __align__(256) __half g_Xa[(size_t)MM * KK];
__device__ __align__(256) __half g_Wb[(size_t)NN * KK];

// ---------------- helpers ----------------
__device__ __forceinline__ uint32_t smem_u32(const void* p) {
    uint32_t a;
    asm("{ .reg .u64 t; cvta.to.shared.u64 t, %1; cvt.u32.u64 %0, t; }"
        : "=r"(a) : "l"(p));
    return a;
}
__device__ __forceinline__ void cp16(uint32_t s, const void* g) {
    asm volatile("cp.async.cg.shared.global [%0], [%1], 16;" :: "r"(s), "l"(g));
}
__device__ __forceinline__ void cp_commit() {
    asm volatile("cp.async.commit_group;" ::: "memory");
}
__device__ __forceinline__ void cp_wait2() {
    asm volatile("cp.async.wait_group 2;" ::: "memory");
}
__device__ __forceinline__ void cp_wait1() {
    asm volatile("cp.async.wait_group 1;" ::: "memory");
}
__device__ __forceinline__ void cp_wait0() {
    asm volatile("cp.async.wait_group 0;" ::: "memory");
}
__device__ __forceinline__ void mma_f16(float* c, const uint32_t* a, const uint32_t* b) {
    asm volatile(
        "mma.sync.aligned.m16n8k16.row.col.f32.f16.f16.f32 "
        "{%0,%1,%2,%3}, {%4,%5,%6,%7}, {%8,%9}, {%0,%1,%2,%3};\n"
        : "+f"(c[0]), "+f"(c[1]), "+f"(c[2]), "+f"(c[3])
        : "r"(a[0]), "r"(a[1]), "r"(a[2]), "r"(a[3]),
          "r"(b[0]), "r"(b[1]));
}
__device__ __forceinline__ uint32_t pack2(float x, float y) {
    __half2 h = __floats2half2_rn(x, y);
    return *reinterpret_cast<uint32_t*>(&h);
}

// ---------------- merged prepass ----------------
// X warp-tile t (t < XTILES): t = ((mb*KT + kt)*2 + kt2)*8 + mt ; 16x16 tile;
//   lane holds uint4 {a00,a10,a01,a11} at t*256 halves + lane*8.
// W warp-tile u = t - XTILES: u = ((nb*KT + kt)*2 + kt2)*32 + nt ; 8x16 tile;
//   lane holds uint2 at u*128 halves + lane*4.
__global__ void prep_all(const float* __restrict__ X, const float* __restrict__ SX,
                         const float* __restrict__ W, const float* __restrict__ WS,
                         const float* __restrict__ OFF) {
    const int lane = threadIdx.x & 31;
    const int gw = (blockIdx.x * blockDim.x + threadIdx.x) >> 5;
    const int nw = (gridDim.x * blockDim.x) >> 5;

    auto do_x = [&](int t) {
        const int mt  = t & 7;
        const int kt2 = (t >> 3) & 1;
        const int kt  = (t >> 4) & 127;
        const int mb  = t >> 11;
        const int r = mb * BM + mt * 16 + (lane >> 2);
        const int k = kt * BK + kt2 * 16 + (lane & 3) * 2;
        const float s0 = __ldg(SX + r);
        const float s1 = __ldg(SX + r + 8);
        const float2 x00 = *reinterpret_cast<const float2*>(X + (size_t)r * KK + k);
        const float2 x10 = *reinterpret_cast<const float2*>(X + (size_t)(r + 8) * KK + k);
        const float2 x01 = *reinterpret_cast<const float2*>(X + (size_t)r * KK + k + 8);
        const float2 x11 = *reinterpret_cast<const float2*>(X + (size_t)(r + 8) * KK + k + 8);
        uint4 v;
        v.x = pack2(x00.x * s0, x00.y * s0);
        v.y = pack2(x10.x * s1, x10.y * s1);
        v.z = pack2(x01.x * s0, x01.y * s0);
        v.w = pack2(x11.x * s1, x11.y * s1);
        *reinterpret_cast<uint4*>(g_Xa + (size_t)t * 256 + lane * 8) = v;
    };

    auto do_w = [&](int u) {
        const int nt  = u & 31;
        const int kt2 = (u >> 5) & 1;
        const int kt  = (u >> 6) & 127;
        const int nb  = u >> 13;
        const int n = nb * BN + nt * 8 + (lane >> 2);
        const int k = kt * BK + kt2 * 16 + (lane & 3) * 2;
        const int g = kt >> 2;               // 32-span lies in one 128-group
        const float ws  = __ldg(WS + (size_t)n * GG + g);
        const float off = __ldg(OFF + (size_t)n * GG + g);
        const float2 w0 = *reinterpret_cast<const float2*>(W + (size_t)n * KK + k);
        const float2 w1 = *reinterpret_cast<const float2*>(W + (size_t)n * KK + k + 8);
        uint2 v;
        v.x = pack2((w0.x - off) * ws, (w0.y - off) * ws);
        v.y = pack2((w1.x - off) * ws, (w1.y - off) * ws);
        *reinterpret_cast<uint2*>(g_Wb + (size_t)u * 128 + lane * 4) = v;
    };

    const int total = XTILES + WTILES;
    // unroll-2 grid stride: two independent tiles in flight per warp iteration
    int t0 = gw * 2;
    const int stride = nw * 2;
    for (; t0 + 1 < total; t0 += stride) {
        const int a = t0, b = t0 + 1;
        if (a < XTILES) do_x(a); else do_w(a - XTILES);
        if (b < XTILES) do_x(b); else do_w(b - XTILES);
    }
    if (t0 < total) {
        if (t0 < XTILES) do_x(t0); else do_w(t0 - XTILES);
    }
}

// ---------------- GEMM: fragment-packed fp16 mma.sync (R4, unchanged) ----------------
__global__ __launch_bounds__(THREADS, 1)
void gemm_frag(float* __restrict__ OUT) {
    extern __shared__ char smem[];
    const uint32_t sbase = smem_u32(smem);

    const int tid = threadIdx.x;
    const int wid = tid >> 5;
    const int lane = tid & 31;
    const int wm = wid >> 2;        // 0..1
    const int wn = wid & 3;         // 0..3

    // CTA swizzle: groups of 8 mb per nb sweep.
    const int bid = blockIdx.x;
    const int grp = bid / (8 * NB);
    const int rem = bid - grp * (8 * NB);
    const int mb = grp * 8 + (rem & 7);
    const int nb = rem >> 3;

    const __half* Ag = g_Xa + (size_t)mb * KT * A_HALVES;
    const __half* Bg = g_Wb + (size_t)nb * KT * B_HALVES;

    float acc[4][8][4];
    #pragma unroll
    for (int i = 0; i < 4; i++)
        #pragma unroll
        for (int j = 0; j < 8; j++)
            #pragma unroll
            for (int c = 0; c < 4; c++) acc[i][j][c] = 0.f;

    auto load_stage = [&](int s, int kt) {
        const uint32_t sa = sbase + s * STAGE_BYTES;
        const char* a = (const char*)(Ag + (size_t)kt * A_HALVES) + tid * 32;
        #pragma unroll
        for (int j = 0; j < 2; j++) cp16(sa + tid * 32 + j * 16, a + j * 16);
        const uint32_t sbb = sa + A_BYTES;
        const char* b = (const char*)(Bg + (size_t)kt * B_HALVES) + tid * 64;
        #pragma unroll
        for (int j = 0; j < 4; j++) cp16(sbb + tid * 64 + j * 16, b + j * 16);
        cp_commit();
    };

    auto compute = [&](int s) {
        const char* As = smem + s * STAGE_BYTES;
        const char* Bs = As + A_BYTES;
        #pragma unroll
        for (int kt2 = 0; kt2 < 2; kt2++) {
            uint4 af[4];
            #pragma unroll
            for (int mi = 0; mi < 4; mi++) {
                const int mt = wm * 4 + mi;
                af[mi] = *reinterpret_cast<const uint4*>(
                    As + (kt2 * 8 + mt) * 512 + lane * 16);
            }
            uint2 bf[8];
            #pragma unroll
            for (int ni = 0; ni < 8; ni++) {
                const int nt = wn * 8 + ni;
                bf[ni] = *reinterpret_cast<const uint2*>(
                    Bs + (kt2 * 32 + nt) * 256 + lane * 8);
            }
            #pragma unroll
            for (int mi = 0; mi < 4; mi++)
                #pragma unroll
                for (int ni = 0; ni < 8; ni++)
                    mma_f16(acc[mi][ni],
                            reinterpret_cast<const uint32_t*>(&af[mi]),
                            reinterpret_cast<const uint32_t*>(&bf[ni]));
        }
    };

    load_stage(0, 0);
    load_stage(1, 1);
    load_stage(2, 2);

    for (int kt = 0; kt < KT; kt++) {
        if (kt < KT - 2)       cp_wait2();
        else if (kt == KT - 2) cp_wait1();
        else                   cp_wait0();
        __syncthreads();
        if (kt + 3 < KT) load_stage((kt + 3) & 3, kt + 3);
        compute(kt & 3);
    }

    // epilogue
    const int m0 = mb * BM + wm * 64;
    const int n0 = nb * BN + wn * 64;
    #pragma unroll
    for (int mi = 0; mi < 4; mi++) {
        const int row = m0 + mi * 16 + (lane >> 2);
        #pragma unroll
        for (int ni = 0; ni < 8; ni++) {
            const int col = n0 + ni * 8 + (lane & 3) * 2;
            float2 v0, v1;
            v0.x = acc[mi][ni][0]; v0.y = acc[mi][ni][1];
            v1.x = acc[mi][ni][2]; v1.y = acc[mi][ni][3];
            *reinterpret_cast<float2*>(OUT + (size_t)row * NN + col)       = v0;
            *reinterpret_cast<float2*>(OUT + (size_t)(row + 8) * NN + col) = v1;
        }
    }
}

// ---------------- launch ----------------
extern "C" void kernel_launch(void* const* d_in, const int* in_sizes, int n_in,
                              void* d_out, int out_size) {
    const float* X   = (const float*)d_in[0];
    const float* SX  = (const float*)d_in[1];
    const float* W   = (const float*)d_in[2];
    const float* WS  = (const float*)d_in[3];
    const float* OFF = (const float*)d_in[4];
    float* OUT = (float*)d_out;

    cudaFuncSetAttribute(gemm_frag,
                         cudaFuncAttributeMaxDynamicSharedMemorySize, SMEM_TOTAL);

    prep_all<<<1776, 256>>>(X, SX, W, WS, OFF);

    gemm_frag<<<MB * NB, THREADS, SMEM_TOTAL>>>(OUT);
}

// round 8
// speedup vs baseline: 1.1690x; 1.0655x over previous
#include <cuda_runtime.h>
#include <cuda_fp16.h>
#include <cstdint>
#include <cstddef>

// ---- problem shapes ----
#define MM 8192
#define NN 11008
#define KK 4096
#define GG 32

// ---- GEMM tiling: 128x128 CTA, 4 warps of 64x64, 2 CTAs/SM ----
#define BM 128
#define BN 128
#define BK 32
#define STAGES 4
#define KT (KK / BK)               // 128
#define THREADS 128

#define NB (NN / BN)               // 86
#define MB (MM / BM)               // 64

// packed A (fp16): per (mb,kt): kt2(2) x mt(8) tiles of 16x16, 256 halves each
#define A_HALVES 4096              // 8 KB per (mb,kt)
#define A_BYTES  (A_HALVES * 2)
// packed B (fp16): per (nb,kt): kt2(2) x nt(16) tiles of 8x16, 128 halves each
#define B_HALVES 4096              // 8 KB per (nb,kt)
#define B_BYTES  (B_HALVES * 2)

#define STAGE_BYTES (A_BYTES + B_BYTES)         // 16384
#define SMEM_TOTAL  (STAGES * STAGE_BYTES)      // 65536 -> 2 CTAs/SM

#define XTILES (MB * KT * 2 * 8)   // 131072
#define WTILES (NB * KT * 2 * 16)  // 352256

// ---- scratch ----
__device__ __align__(256) __half g_Xa[(size_t)MM * KK];
__device__ __align__(256) __half g_Wb[(size_t)NN * KK];

// ---------------- helpers ----------------
__device__ __forceinline__ uint32_t smem_u32(const void* p) {
    uint32_t a;
    asm("{ .reg .u64 t; cvta.to.shared.u64 t, %1; cvt.u32.u64 %0, t; }"
        : "=r"(a) : "l"(p));
    return a;
}
__device__ __forceinline__ void cp16(uint32_t s, const void* g) {
    asm volatile("cp.async.cg.shared.global [%0], [%1], 16;" :: "r"(s), "l"(g));
}
__device__ __forceinline__ void cp_commit() {
    asm volatile("cp.async.commit_group;" ::: "memory");
}
__device__ __forceinline__ void cp_wait2() {
    asm volatile("cp.async.wait_group 2;" ::: "memory");
}
__device__ __forceinline__ void cp_wait1() {
    asm volatile("cp.async.wait_group 1;" ::: "memory");
}
__device__ __forceinline__ void cp_wait0() {
    asm volatile("cp.async.wait_group 0;" ::: "memory");
}
__device__ __forceinline__ void mma_f16(float* c, const uint32_t* a, const uint32_t* b) {
    asm volatile(
        "mma.sync.aligned.m16n8k16.row.col.f32.f16.f16.f32 "
        "{%0,%1,%2,%3}, {%4,%5,%6,%7}, {%8,%9}, {%0,%1,%2,%3};\n"
        : "+f"(c[0]), "+f"(c[1]), "+f"(c[2]), "+f"(c[3])
        : "r"(a[0]), "r"(a[1]), "r"(a[2]), "r"(a[3]),
          "r"(b[0]), "r"(b[1]));
}
__device__ __forceinline__ uint32_t pack2(float x, float y) {
    __half2 h = __floats2half2_rn(x, y);
    return *reinterpret_cast<uint32_t*>(&h);
}

// ---------------- prepass: X * sx -> fragment-packed fp16 ----------------
// t = ((mb*KT + kt)*2 + kt2)*8 + mt ; 16x16 tile; lane holds uint4 at t*256 + lane*8
__global__ void prep_x(const float* __restrict__ X, const float* __restrict__ SX) {
    const int lane = threadIdx.x & 31;
    const int gw = (blockIdx.x * blockDim.x + threadIdx.x) >> 5;
    const int nw = (gridDim.x * blockDim.x) >> 5;
    for (int t = gw; t < XTILES; t += nw) {
        const int mt  = t & 7;
        const int kt2 = (t >> 3) & 1;
        const int kt  = (t >> 4) & 127;
        const int mb  = t >> 11;
        const int r = mb * BM + mt * 16 + (lane >> 2);
        const int k = kt * BK + kt2 * 16 + (lane & 3) * 2;
        const float s0 = __ldg(SX + r);
        const float s1 = __ldg(SX + r + 8);
        const float2 x00 = *reinterpret_cast<const float2*>(X + (size_t)r * KK + k);
        const float2 x10 = *reinterpret_cast<const float2*>(X + (size_t)(r + 8) * KK + k);
        const float2 x01 = *reinterpret_cast<const float2*>(X + (size_t)r * KK + k + 8);
        const float2 x11 = *reinterpret_cast<const float2*>(X + (size_t)(r + 8) * KK + k + 8);
        uint4 v;
        v.x = pack2(x00.x * s0, x00.y * s0);
        v.y = pack2(x10.x * s1, x10.y * s1);
        v.z = pack2(x01.x * s0, x01.y * s0);
        v.w = pack2(x11.x * s1, x11.y * s1);
        *reinterpret_cast<uint4*>(g_Xa + (size_t)t * 256 + lane * 8) = v;
    }
}

// ---------------- prepass: (W-off)*ws -> fragment-packed fp16 ----------------
// u = ((nb*KT + kt)*2 + kt2)*16 + nt ; 8x16 tile; lane holds uint2 at u*128 + lane*4
__global__ void prep_w(const float* __restrict__ W, const float* __restrict__ WS,
                       const float* __restrict__ OFF) {
    const int lane = threadIdx.x & 31;
    const int gw = (blockIdx.x * blockDim.x + threadIdx.x) >> 5;
    const int nw = (gridDim.x * blockDim.x) >> 5;
    for (int u = gw; u < WTILES; u += nw) {
        const int nt  = u & 15;
        const int kt2 = (u >> 4) & 1;
        const int kt  = (u >> 5) & 127;
        const int nb  = u >> 12;
        const int n = nb * BN + nt * 8 + (lane >> 2);
        const int k = kt * BK + kt2 * 16 + (lane & 3) * 2;
        const int g = kt >> 2;               // 32-span lies in one 128-group
        const float ws  = __ldg(WS + (size_t)n * GG + g);
        const float off = __ldg(OFF + (size_t)n * GG + g);
        const float2 w0 = *reinterpret_cast<const float2*>(W + (size_t)n * KK + k);
        const float2 w1 = *reinterpret_cast<const float2*>(W + (size_t)n * KK + k + 8);
        uint2 v;
        v.x = pack2((w0.x - off) * ws, (w0.y - off) * ws);
        v.y = pack2((w1.x - off) * ws, (w1.y - off) * ws);
        *reinterpret_cast<uint2*>(g_Wb + (size_t)u * 128 + lane * 4) = v;
    }
}

// ---------------- GEMM: 128x128 CTA, 2 CTAs/SM ----------------
__global__ __launch_bounds__(THREADS, 2)
void gemm_frag(float* __restrict__ OUT) {
    extern __shared__ char smem[];
    const uint32_t sbase = smem_u32(smem);

    const int tid = threadIdx.x;
    const int wid = tid >> 5;       // 0..3
    const int lane = tid & 31;
    const int wm = wid >> 1;        // 0..1
    const int wn = wid & 1;         // 0..1

    // CTA swizzle: groups of 8 mb per nb sweep (wave working set ~96MB -> L2).
    const int bid = blockIdx.x;
    const int grp = bid / (8 * NB);
    const int rem = bid - grp * (8 * NB);
    const int mb = grp * 8 + (rem & 7);
    const int nb = rem >> 3;

    const __half* Ag = g_Xa + (size_t)mb * KT * A_HALVES;
    const __half* Bg = g_Wb + (size_t)nb * KT * B_HALVES;

    float acc[4][8][4];
    #pragma unroll
    for (int i = 0; i < 4; i++)
        #pragma unroll
        for (int j = 0; j < 8; j++)
            #pragma unroll
            for (int c = 0; c < 4; c++) acc[i][j][c] = 0.f;

    auto load_stage = [&](int s, int kt) {
        const uint32_t sa = sbase + s * STAGE_BYTES;
        const char* a = (const char*)(Ag + (size_t)kt * A_HALVES) + tid * 64;
        #pragma unroll
        for (int j = 0; j < 4; j++) cp16(sa + tid * 64 + j * 16, a + j * 16);
        const uint32_t sbb = sa + A_BYTES;
        const char* b = (const char*)(Bg + (size_t)kt * B_HALVES) + tid * 64;
        #pragma unroll
        for (int j = 0; j < 4; j++) cp16(sbb + tid * 64 + j * 16, b + j * 16);
        cp_commit();
    };

    auto compute = [&](int s) {
        const char* As = smem + s * STAGE_BYTES;
        const char* Bs = As + A_BYTES;
        #pragma unroll
        for (int kt2 = 0; kt2 < 2; kt2++) {
            uint4 af[4];
            #pragma unroll
            for (int mi = 0; mi < 4; mi++) {
                const int mt = wm * 4 + mi;
                af[mi] = *reinterpret_cast<const uint4*>(
                    As + (kt2 * 8 + mt) * 512 + lane * 16);
            }
            uint2 bf[8];
            #pragma unroll
            for (int ni = 0; ni < 8; ni++) {
                const int nt = wn * 8 + ni;
                bf[ni] = *reinterpret_cast<const uint2*>(
                    Bs + (kt2 * 16 + nt) * 256 + lane * 8);
            }
            #pragma unroll
            for (int mi = 0; mi < 4; mi++)
                #pragma unroll
                for (int ni = 0; ni < 8; ni++)
                    mma_f16(acc[mi][ni],
                            reinterpret_cast<const uint32_t*>(&af[mi]),
                            reinterpret_cast<const uint32_t*>(&bf[ni]));
        }
    };

    load_stage(0, 0);
    load_stage(1, 1);
    load_stage(2, 2);

    for (int kt = 0; kt < KT; kt++) {
        if (kt < KT - 2)       cp_wait2();
        else if (kt == KT - 2) cp_wait1();
        else                   cp_wait0();
        __syncthreads();
        if (kt + 3 < KT) load_stage((kt + 3) & 3, kt + 3);
        compute(kt & 3);
    }

    // epilogue
    const int m0 = mb * BM + wm * 64;
    const int n0 = nb * BN + wn * 64;
    #pragma unroll
    for (int mi = 0; mi < 4; mi++) {
        const int row = m0 + mi * 16 + (lane >> 2);
        #pragma unroll
        for (int ni = 0; ni < 8; ni++) {
            const int col = n0 + ni * 8 + (lane & 3) * 2;
            float2 v0, v1;
            v0.x = acc[mi][ni][0]; v0.y = acc[mi][ni][1];
            v1.x = acc[mi][ni][2]; v1.y = acc[mi][ni][3];
            *reinterpret_cast<float2*>(OUT + (size_t)row * NN + col)       = v0;
            *reinterpret_cast<float2*>(OUT + (size_t)(row + 8) * NN + col) = v1;
        }
    }
}

// ---------------- launch ----------------
extern "C" void kernel_launch(void* const* d_in, const int* in_sizes, int n_in,
                              void* d_out, int out_size) {
    const float* X   = (const float*)d_in[0];
    const float* SX  = (const float*)d_in[1];
    const float* W   = (const float*)d_in[2];
    const float* WS  = (const float*)d_in[3];
    const float* OFF = (const float*)d_in[4];
    float* OUT = (float*)d_out;

    cudaFuncSetAttribute(gemm_frag,
                         cudaFuncAttributeMaxDynamicSharedMemorySize, SMEM_TOTAL);

    prep_x<<<2048, 256>>>(X, SX);
    prep_w<<<2048, 256>>>(W, WS, OFF);

    gemm_frag<<<MB * NB, THREADS, SMEM_TOTAL>>>(OUT);
}

// round 9
// speedup vs baseline: 1.7829x; 1.5251x over previous
#include <cuda_runtime.h>
#include <cuda_fp16.h>
#include <cstdint>
#include <cstddef>

// ---- problem shapes ----
#define MM 8192
#define NN 11008
#define KK 4096
#define GG 32

// ---- GEMM tiling: 128x256 CTA, 8 warps of 64x64, BK=64 two-stage ----
#define BM 128
#define BN 256
#define BKP 64                      // K per stage (two 32-sub-tiles)
#define KP (KK / BKP)               // 64 stages of K
#define THREADS 256

#define NB (NN / BN)                // 43
#define MB (MM / BM)                // 64

// packed A (fp16): per (mb,kt32): kt2(2) x mt(8) tiles of 16x16 = 8 KB
#define A_HALVES 4096
#define A_KT_BYTES (A_HALVES * 2)   // 8192
// packed B (fp16): per (nb,kt32): kt2(2) x nt(32) tiles of 8x16 = 16 KB
#define B_HALVES 8192
#define B_KT_BYTES (B_HALVES * 2)   // 16384

// stage layout: [A kt0 8K][A kt1 8K][B kt0 16K][B kt1 16K] = 48 KB
#define STAGE_A_BYTES (2 * A_KT_BYTES)            // 16384
#define STAGE_BYTES   (STAGE_A_BYTES + 2 * B_KT_BYTES)  // 49152
#define SMEM_TOTAL    (2 * STAGE_BYTES)           // 98304

#define XTILES (MB * 128 * 2 * 8)   // 131072  (kt32 index 0..127)
#define WTILES (NB * 128 * 2 * 32)  // 352256

// ---- scratch ----
__device__ __align__(256) __half g_Xa[(size_t)MM * KK];
__device__ __align__(256) __half g_Wb[(size_t)NN * KK];

// ---------------- helpers ----------------
__device__ __forceinline__ void cp16(uint32_t s, const void* g) {
    asm volatile("cp.async.cg.shared.global [%0], [%1], 16;" :: "r"(s), "l"(g));
}
__device__ __forceinline__ uint32_t smem_u32(const void* p) {
    uint32_t a;
    asm("{ .reg .u64 t; cvta.to.shared.u64 t, %1; cvt.u32.u64 %0, t; }"
        : "=r"(a) : "l"(p));
    return a;
}
__device__ __forceinline__ void cp_commit() {
    asm volatile("cp.async.commit_group;" ::: "memory");
}
__device__ __forceinline__ void cp_wait0() {
    asm volatile("cp.async.wait_group 0;" ::: "memory");
}
__device__ __forceinline__ void mma_f16(float* c, const uint32_t* a, const uint32_t* b) {
    asm volatile(
        "mma.sync.aligned.m16n8k16.row.col.f32.f16.f16.f32 "
        "{%0,%1,%2,%3}, {%4,%5,%6,%7}, {%8,%9}, {%0,%1,%2,%3};\n"
        : "+f"(c[0]), "+f"(c[1]), "+f"(c[2]), "+f"(c[3])
        : "r"(a[0]), "r"(a[1]), "r"(a[2]), "r"(a[3]),
          "r"(b[0]), "r"(b[1]));
}
__device__ __forceinline__ uint32_t pack2(float x, float y) {
    __half2 h = __floats2half2_rn(x, y);
    return *reinterpret_cast<uint32_t*>(&h);
}

// ---------------- prepass: X * sx -> fragment-packed fp16 (R4 layout) ----------------
// t = ((mb*128 + kt32)*2 + kt2)*8 + mt ; lane holds uint4 at t*256 + lane*8
__global__ void prep_x(const float* __restrict__ X, const float* __restrict__ SX) {
    const int lane = threadIdx.x & 31;
    const int gw = (blockIdx.x * blockDim.x + threadIdx.x) >> 5;
    const int nw = (gridDim.x * blockDim.x) >> 5;
    for (int t = gw; t < XTILES; t += nw) {
        const int mt  = t & 7;
        const int kt2 = (t >> 3) & 1;
        const int kt  = (t >> 4) & 127;
        const int mb  = t >> 11;
        const int r = mb * BM + mt * 16 + (lane >> 2);
        const int k = kt * 32 + kt2 * 16 + (lane & 3) * 2;
        const float s0 = __ldg(SX + r);
        const float s1 = __ldg(SX + r + 8);
        const float2 x00 = *reinterpret_cast<const float2*>(X + (size_t)r * KK + k);
        const float2 x10 = *reinterpret_cast<const float2*>(X + (size_t)(r + 8) * KK + k);
        const float2 x01 = *reinterpret_cast<const float2*>(X + (size_t)r * KK + k + 8);
        const float2 x11 = *reinterpret_cast<const float2*>(X + (size_t)(r + 8) * KK + k + 8);
        uint4 v;
        v.x = pack2(x00.x * s0, x00.y * s0);
        v.y = pack2(x10.x * s1, x10.y * s1);
        v.z = pack2(x01.x * s0, x01.y * s0);
        v.w = pack2(x11.x * s1, x11.y * s1);
        *reinterpret_cast<uint4*>(g_Xa + (size_t)t * 256 + lane * 8) = v;
    }
}

// ---------------- prepass: (W-off)*ws -> fragment-packed fp16 (R4 layout) ----------------
// u = ((nb*128 + kt32)*2 + kt2)*32 + nt ; lane holds uint2 at u*128 + lane*4
__global__ void prep_w(const float* __restrict__ W, const float* __restrict__ WS,
                       const float* __restrict__ OFF) {
    const int lane = threadIdx.x & 31;
    const int gw = (blockIdx.x * blockDim.x + threadIdx.x) >> 5;
    const int nw = (gridDim.x * blockDim.x) >> 5;
    for (int u = gw; u < WTILES; u += nw) {
        const int nt  = u & 31;
        const int kt2 = (u >> 5) & 1;
        const int kt  = (u >> 6) & 127;
        const int nb  = u >> 13;
        const int n = nb * BN + nt * 8 + (lane >> 2);
        const int k = kt * 32 + kt2 * 16 + (lane & 3) * 2;
        const int g = kt >> 2;
        const float ws  = __ldg(WS + (size_t)n * GG + g);
        const float off = __ldg(OFF + (size_t)n * GG + g);
        const float2 w0 = *reinterpret_cast<const float2*>(W + (size_t)n * KK + k);
        const float2 w1 = *reinterpret_cast<const float2*>(W + (size_t)n * KK + k + 8);
        uint2 v;
        v.x = pack2((w0.x - off) * ws, (w0.y - off) * ws);
        v.y = pack2((w1.x - off) * ws, (w1.y - off) * ws);
        *reinterpret_cast<uint2*>(g_Wb + (size_t)u * 128 + lane * 4) = v;
    }
}

// ---------------- GEMM: BK=64 two-stage double buffer ----------------
__global__ __launch_bounds__(THREADS, 1)
void gemm_frag(float* __restrict__ OUT) {
    extern __shared__ char smem[];
    const uint32_t sbase = smem_u32(smem);

    const int tid = threadIdx.x;
    const int wid = tid >> 5;
    const int lane = tid & 31;
    const int wm = wid >> 2;        // 0..1
    const int wn = wid & 3;         // 0..3

    // CTA swizzle: groups of 8 mb per nb sweep.
    const int bid = blockIdx.x;
    const int grp = bid / (8 * NB);
    const int rem = bid - grp * (8 * NB);
    const int mb = grp * 8 + (rem & 7);
    const int nb = rem >> 3;

    const __half* Ag = g_Xa + (size_t)mb * 128 * A_HALVES;   // per kt32: A_HALVES
    const __half* Bg = g_Wb + (size_t)nb * 128 * B_HALVES;

    float acc[4][8][4];
    #pragma unroll
    for (int i = 0; i < 4; i++)
        #pragma unroll
        for (int j = 0; j < 8; j++)
            #pragma unroll
            for (int c = 0; c < 4; c++) acc[i][j][c] = 0.f;

    // stage s holds kt32 pair {2t, 2t+1}
    auto load_stage = [&](int s, int t) {
        const uint32_t st = sbase + s * STAGE_BYTES;
        #pragma unroll
        for (int h = 0; h < 2; h++) {
            const char* a = (const char*)(Ag + (size_t)(2 * t + h) * A_HALVES) + tid * 32;
            const uint32_t sa = st + h * A_KT_BYTES + tid * 32;
            #pragma unroll
            for (int j = 0; j < 2; j++) cp16(sa + j * 16, a + j * 16);
            const char* b = (const char*)(Bg + (size_t)(2 * t + h) * B_HALVES) + tid * 64;
            const uint32_t sb2 = st + STAGE_A_BYTES + h * B_KT_BYTES + tid * 64;
            #pragma unroll
            for (int j = 0; j < 4; j++) cp16(sb2 + j * 16, b + j * 16);
        }
        cp_commit();
    };

    auto compute = [&](int s) {
        const char* stg = smem + s * STAGE_BYTES;
        #pragma unroll
        for (int h = 0; h < 2; h++) {
            const char* As = stg + h * A_KT_BYTES;
            const char* Bs = stg + STAGE_A_BYTES + h * B_KT_BYTES;
            #pragma unroll
            for (int kt2 = 0; kt2 < 2; kt2++) {
                uint4 af[4];
                #pragma unroll
                for (int mi = 0; mi < 4; mi++) {
                    const int mt = wm * 4 + mi;
                    af[mi] = *reinterpret_cast<const uint4*>(
                        As + (kt2 * 8 + mt) * 512 + lane * 16);
                }
                uint2 bf[8];
                #pragma unroll
                for (int ni = 0; ni < 8; ni++) {
                    const int nt = wn * 8 + ni;
                    bf[ni] = *reinterpret_cast<const uint2*>(
                        Bs + (kt2 * 32 + nt) * 256 + lane * 8);
                }
                #pragma unroll
                for (int mi = 0; mi < 4; mi++)
                    #pragma unroll
                    for (int ni = 0; ni < 8; ni++)
                        mma_f16(acc[mi][ni],
                                reinterpret_cast<const uint32_t*>(&af[mi]),
                                reinterpret_cast<const uint32_t*>(&bf[ni]));
            }
        }
    };

    // pipeline: wait0 -> barrier -> prefetch next -> compute current
    load_stage(0, 0);
    #pragma unroll 1
    for (int t = 0; t < KP; t++) {
        cp_wait0();                 // this thread's copies for stage t landed
        __syncthreads();            // all threads' copies visible; all done compute t-1
        if (t + 1 < KP) load_stage((t + 1) & 1, t + 1);  // safe: buffer free
        compute(t & 1);
    }

    // epilogue
    const int m0 = mb * BM + wm * 64;
    const int n0 = nb * BN + wn * 64;
    #pragma unroll
    for (int mi = 0; mi < 4; mi++) {
        const int row = m0 + mi * 16 + (lane >> 2);
        #pragma unroll
        for (int ni = 0; ni < 8; ni++) {
            const int col = n0 + ni * 8 + (lane & 3) * 2;
            float2 v0, v1;
            v0.x = acc[mi][ni][0]; v0.y = acc[mi][ni][1];
            v1.x = acc[mi][ni][2]; v1.y = acc[mi][ni][3];
            *reinterpret_cast<float2*>(OUT + (size_t)row * NN + col)       = v0;
            *reinterpret_cast<float2*>(OUT + (size_t)(row + 8) * NN + col) = v1;
        }
    }
}

// ---------------- launch ----------------
extern "C" void kernel_launch(void* const* d_in, const int* in_sizes, int n_in,
                              void* d_out, int out_size) {
    const float* X   = (const float*)d_in[0];
    const float* SX  = (const float*)d_in[1];
    const float* W   = (const float*)d_in[2];
    const float* WS  = (const float*)d_in[3];
    const float* OFF = (const float*)d_in[4];
    float* OUT = (float*)d_out;

    cudaFuncSetAttribute(gemm_frag,
                         cudaFuncAttributeMaxDynamicSharedMemorySize, SMEM_TOTAL);

    prep_x<<<2048, 256>>>(X, SX);
    prep_w<<<2048, 256>>>(W, WS, OFF);

    gemm_frag<<<MB * NB, THREADS, SMEM_TOTAL>>>(OUT);
}

// round 10
// speedup vs baseline: 1.8423x; 1.0333x over previous
#include <cuda_runtime.h>
#include <cuda_fp16.h>
#include <cstdint>
#include <cstddef>

// ---- problem shapes ----
#define MM 8192
#define NN 11008
#define KK 4096
#define GG 32

// ---- GEMM tiling: 128x256 CTA, 8 warps of 64x64, BK=128 two-stage ----
#define BM 128
#define BN 256
#define BKP 128                     // K per stage (four 32-sub-tiles)
#define KP (KK / BKP)               // 32 stages
#define THREADS 256

#define NB (NN / BN)                // 43
#define MB (MM / BM)                // 64

// packed A (fp16): per (mb,kt32): kt2(2) x mt(8) tiles of 16x16 = 8 KB
#define A_HALVES 4096
#define A_KT_BYTES (A_HALVES * 2)   // 8192
// packed B (fp16): per (nb,kt32): kt2(2) x nt(32) tiles of 8x16 = 16 KB
#define B_HALVES 8192
#define B_KT_BYTES (B_HALVES * 2)   // 16384

// stage layout: [A kt0..kt3 4x8K][B kt0..kt3 4x16K] = 96 KB
#define STAGE_A_BYTES (4 * A_KT_BYTES)                 // 32768
#define STAGE_BYTES   (STAGE_A_BYTES + 4 * B_KT_BYTES) // 98304
#define SMEM_TOTAL    (2 * STAGE_BYTES)                // 196608

#define XTILES (MB * 128 * 2 * 8)   // 131072  (kt32 index 0..127)
#define WTILES (NB * 128 * 2 * 32)  // 352256

// ---- scratch ----
__device__ __align__(256) __half g_Xa[(size_t)MM * KK];
__device__ __align__(256) __half g_Wb[(size_t)NN * KK];

// ---------------- helpers ----------------
__device__ __forceinline__ void cp16(uint32_t s, const void* g) {
    asm volatile("cp.async.cg.shared.global [%0], [%1], 16;" :: "r"(s), "l"(g));
}
__device__ __forceinline__ uint32_t smem_u32(const void* p) {
    uint32_t a;
    asm("{ .reg .u64 t; cvta.to.shared.u64 t, %1; cvt.u32.u64 %0, t; }"
        : "=r"(a) : "l"(p));
    return a;
}
__device__ __forceinline__ void cp_commit() {
    asm volatile("cp.async.commit_group;" ::: "memory");
}
__device__ __forceinline__ void cp_wait0() {
    asm volatile("cp.async.wait_group 0;" ::: "memory");
}
__device__ __forceinline__ void mma_f16(float* c, const uint32_t* a, const uint32_t* b) {
    asm volatile(
        "mma.sync.aligned.m16n8k16.row.col.f32.f16.f16.f32 "
        "{%0,%1,%2,%3}, {%4,%5,%6,%7}, {%8,%9}, {%0,%1,%2,%3};\n"
        : "+f"(c[0]), "+f"(c[1]), "+f"(c[2]), "+f"(c[3])
        : "r"(a[0]), "r"(a[1]), "r"(a[2]), "r"(a[3]),
          "r"(b[0]), "r"(b[1]));
}
__device__ __forceinline__ uint32_t pack2(float x, float y) {
    __half2 h = __floats2half2_rn(x, y);
    return *reinterpret_cast<uint32_t*>(&h);
}

// ---------------- prepass: X * sx -> fragment-packed fp16 ----------------
// t = ((mb*128 + kt32)*2 + kt2)*8 + mt ; lane holds uint4 at t*256 + lane*8
__global__ void prep_x(const float* __restrict__ X, const float* __restrict__ SX) {
    const int lane = threadIdx.x & 31;
    const int gw = (blockIdx.x * blockDim.x + threadIdx.x) >> 5;
    const int nw = (gridDim.x * blockDim.x) >> 5;
    for (int t = gw; t < XTILES; t += nw) {
        const int mt  = t & 7;
        const int kt2 = (t >> 3) & 1;
        const int kt  = (t >> 4) & 127;
        const int mb  = t >> 11;
        const int r = mb * BM + mt * 16 + (lane >> 2);
        const int k = kt * 32 + kt2 * 16 + (lane & 3) * 2;
        const float s0 = __ldg(SX + r);
        const float s1 = __ldg(SX + r + 8);
        const float2 x00 = *reinterpret_cast<const float2*>(X + (size_t)r * KK + k);
        const float2 x10 = *reinterpret_cast<const float2*>(X + (size_t)(r + 8) * KK + k);
        const float2 x01 = *reinterpret_cast<const float2*>(X + (size_t)r * KK + k + 8);
        const float2 x11 = *reinterpret_cast<const float2*>(X + (size_t)(r + 8) * KK + k + 8);
        uint4 v;
        v.x = pack2(x00.x * s0, x00.y * s0);
        v.y = pack2(x10.x * s1, x10.y * s1);
        v.z = pack2(x01.x * s0, x01.y * s0);
        v.w = pack2(x11.x * s1, x11.y * s1);
        *reinterpret_cast<uint4*>(g_Xa + (size_t)t * 256 + lane * 8) = v;
    }
}

// ---------------- prepass: (W-off)*ws -> fragment-packed fp16 (unroll-2) ----------------
// u = ((nb*128 + kt32)*2 + kt2)*32 + nt ; lane holds uint2 at u*128 + lane*4
__global__ void prep_w(const float* __restrict__ W, const float* __restrict__ WS,
                       const float* __restrict__ OFF) {
    const int lane = threadIdx.x & 31;
    const int gw = (blockIdx.x * blockDim.x + threadIdx.x) >> 5;
    const int nw = (gridDim.x * blockDim.x) >> 5;

    auto do_w = [&](int u) {
        const int nt  = u & 31;
        const int kt2 = (u >> 5) & 1;
        const int kt  = (u >> 6) & 127;
        const int nb  = u >> 13;
        const int n = nb * BN + nt * 8 + (lane >> 2);
        const int k = kt * 32 + kt2 * 16 + (lane & 3) * 2;
        const int g = kt >> 2;
        const float ws  = __ldg(WS + (size_t)n * GG + g);
        const float off = __ldg(OFF + (size_t)n * GG + g);
        const float2 w0 = *reinterpret_cast<const float2*>(W + (size_t)n * KK + k);
        const float2 w1 = *reinterpret_cast<const float2*>(W + (size_t)n * KK + k + 8);
        uint2 v;
        v.x = pack2((w0.x - off) * ws, (w0.y - off) * ws);
        v.y = pack2((w1.x - off) * ws, (w1.y - off) * ws);
        *reinterpret_cast<uint2*>(g_Wb + (size_t)u * 128 + lane * 4) = v;
    };

    int u = gw * 2;
    const int stride = nw * 2;
    for (; u + 1 < WTILES; u += stride) {
        do_w(u);
        do_w(u + 1);
    }
    if (u < WTILES) do_w(u);
}

// ---------------- GEMM: BK=128 two-stage double buffer ----------------
__global__ __launch_bounds__(THREADS, 1)
void gemm_frag(float* __restrict__ OUT) {
    extern __shared__ char smem[];
    const uint32_t sbase = smem_u32(smem);

    const int tid = threadIdx.x;
    const int wid = tid >> 5;
    const int lane = tid & 31;
    const int wm = wid >> 2;        // 0..1
    const int wn = wid & 3;         // 0..3

    // CTA swizzle: groups of 8 mb per nb sweep.
    const int bid = blockIdx.x;
    const int grp = bid / (8 * NB);
    const int rem = bid - grp * (8 * NB);
    const int mb = grp * 8 + (rem & 7);
    const int nb = rem >> 3;

    const __half* Ag = g_Xa + (size_t)mb * 128 * A_HALVES;   // per kt32: A_HALVES
    const __half* Bg = g_Wb + (size_t)nb * 128 * B_HALVES;

    float acc[4][8][4];
    #pragma unroll
    for (int i = 0; i < 4; i++)
        #pragma unroll
        for (int j = 0; j < 8; j++)
            #pragma unroll
            for (int c = 0; c < 4; c++) acc[i][j][c] = 0.f;

    // stage s holds kt32 quad {4t .. 4t+3}
    auto load_stage = [&](int s, int t) {
        const uint32_t st = sbase + s * STAGE_BYTES;
        #pragma unroll
        for (int h = 0; h < 4; h++) {
            const char* a = (const char*)(Ag + (size_t)(4 * t + h) * A_HALVES) + tid * 32;
            const uint32_t sa = st + h * A_KT_BYTES + tid * 32;
            #pragma unroll
            for (int j = 0; j < 2; j++) cp16(sa + j * 16, a + j * 16);
            const char* b = (const char*)(Bg + (size_t)(4 * t + h) * B_HALVES) + tid * 64;
            const uint32_t sb2 = st + STAGE_A_BYTES + h * B_KT_BYTES + tid * 64;
            #pragma unroll
            for (int j = 0; j < 4; j++) cp16(sb2 + j * 16, b + j * 16);
        }
        cp_commit();
    };

    auto compute = [&](int s) {
        const char* stg = smem + s * STAGE_BYTES;
        #pragma unroll
        for (int h = 0; h < 4; h++) {
            const char* As = stg + h * A_KT_BYTES;
            const char* Bs = stg + STAGE_A_BYTES + h * B_KT_BYTES;
            #pragma unroll
            for (int kt2 = 0; kt2 < 2; kt2++) {
                uint4 af[4];
                #pragma unroll
                for (int mi = 0; mi < 4; mi++) {
                    const int mt = wm * 4 + mi;
                    af[mi] = *reinterpret_cast<const uint4*>(
                        As + (kt2 * 8 + mt) * 512 + lane * 16);
                }
                uint2 bf[8];
                #pragma unroll
                for (int ni = 0; ni < 8; ni++) {
                    const int nt = wn * 8 + ni;
                    bf[ni] = *reinterpret_cast<const uint2*>(
                        Bs + (kt2 * 32 + nt) * 256 + lane * 8);
                }
                #pragma unroll
                for (int mi = 0; mi < 4; mi++)
                    #pragma unroll
                    for (int ni = 0; ni < 8; ni++)
                        mma_f16(acc[mi][ni],
                                reinterpret_cast<const uint32_t*>(&af[mi]),
                                reinterpret_cast<const uint32_t*>(&bf[ni]));
            }
        }
    };

    // pipeline: wait0 -> barrier -> prefetch next -> compute current
    load_stage(0, 0);
    #pragma unroll 1
    for (int t = 0; t < KP; t++) {
        cp_wait0();                 // this thread's copies for stage t landed
        __syncthreads();            // all threads' copies visible; compute t-1 done
        if (t + 1 < KP) load_stage((t + 1) & 1, t + 1);  // buffer free
        compute(t & 1);
    }

    // epilogue
    const int m0 = mb * BM + wm * 64;
    const int n0 = nb * BN + wn * 64;
    #pragma unroll
    for (int mi = 0; mi < 4; mi++) {
        const int row = m0 + mi * 16 + (lane >> 2);
        #pragma unroll
        for (int ni = 0; ni < 8; ni++) {
            const int col = n0 + ni * 8 + (lane & 3) * 2;
            float2 v0, v1;
            v0.x = acc[mi][ni][0]; v0.y = acc[mi][ni][1];
            v1.x = acc[mi][ni][2]; v1.y = acc[mi][ni][3];
            *reinterpret_cast<float2*>(OUT + (size_t)row * NN + col)       = v0;
            *reinterpret_cast<float2*>(OUT + (size_t)(row + 8) * NN + col) = v1;
        }
    }
}

// ---------------- launch ----------------
extern "C" void kernel_launch(void* const* d_in, const int* in_sizes, int n_in,
                              void* d_out, int out_size) {
    const float* X   = (const float*)d_in[0];
    const float* SX  = (const float*)d_in[1];
    const float* W   = (const float*)d_in[2];
    const float* WS  = (const float*)d_in[3];
    const float* OFF = (const float*)d_in[4];
    float* OUT = (float*)d_out;

    cudaFuncSetAttribute(gemm_frag,
                         cudaFuncAttributeMaxDynamicSharedMemorySize, SMEM_TOTAL);

    prep_x<<<2048, 256>>>(X, SX);
    prep_w<<<2048, 256>>>(W, WS, OFF);

    gemm_frag<<<MB * NB, THREADS, SMEM_TOTAL>>>(OUT);
}

// round 11
// speedup vs baseline: 1.8597x; 1.0095x over previous
#include <cuda_runtime.h>
#include <cuda_fp16.h>
#include <cstdint>
#include <cstddef>

// ---- problem shapes ----
#define MM 8192
#define NN 11008
#define KK 4096
#define GG 32

// ---- GEMM tiling: 128x256 CTA, 8 warps of 64x64, BK=128 two-stage, persistent ----
#define BM 128
#define BN 256
#define KP 32                       // 32 stages of BK=128
#define THREADS 256

#define NB (NN / BN)                // 43
#define MB (MM / BM)                // 64
#define NTILES (MB * NB)            // 2752
#define GRID 148                    // persistent: 1 CTA per SM

#define A_HALVES 4096               // per (mb,kt32): 8 KB
#define A_KT_BYTES (A_HALVES * 2)
#define B_HALVES 8192               // per (nb,kt32): 16 KB
#define B_KT_BYTES (B_HALVES * 2)

#define STAGE_A_BYTES (4 * A_KT_BYTES)                 // 32768
#define STAGE_BYTES   (STAGE_A_BYTES + 4 * B_KT_BYTES) // 98304
#define SMEM_TOTAL    (2 * STAGE_BYTES)                // 196608

#define XTILES (MB * 128 * 2 * 8)   // 131072
#define WTILES (NB * 128 * 2 * 32)  // 352256

// ---- scratch ----
__device__ __align__(256) __half g_Xa[(size_t)MM * KK];
__device__ __align__(256) __half g_Wb[(size_t)NN * KK];

// ---------------- helpers ----------------
__device__ __forceinline__ void cp16(uint32_t s, const void* g) {
    asm volatile("cp.async.cg.shared.global [%0], [%1], 16;" :: "r"(s), "l"(g));
}
__device__ __forceinline__ uint32_t smem_u32(const void* p) {
    uint32_t a;
    asm("{ .reg .u64 t; cvta.to.shared.u64 t, %1; cvt.u32.u64 %0, t; }"
        : "=r"(a) : "l"(p));
    return a;
}
__device__ __forceinline__ void cp_commit() {
    asm volatile("cp.async.commit_group;" ::: "memory");
}
__device__ __forceinline__ void cp_wait0() {
    asm volatile("cp.async.wait_group 0;" ::: "memory");
}
__device__ __forceinline__ void mma_f16(float* c, const uint32_t* a, const uint32_t* b) {
    asm volatile(
        "mma.sync.aligned.m16n8k16.row.col.f32.f16.f16.f32 "
        "{%0,%1,%2,%3}, {%4,%5,%6,%7}, {%8,%9}, {%0,%1,%2,%3};\n"
        : "+f"(c[0]), "+f"(c[1]), "+f"(c[2]), "+f"(c[3])
        : "r"(a[0]), "r"(a[1]), "r"(a[2]), "r"(a[3]),
          "r"(b[0]), "r"(b[1]));
}
__device__ __forceinline__ uint32_t pack2(float x, float y) {
    __half2 h = __floats2half2_rn(x, y);
    return *reinterpret_cast<uint32_t*>(&h);
}

// ---------------- merged prepass (X tiles, then W tiles; unroll-2) ----------------
__global__ void prep_all(const float* __restrict__ X, const float* __restrict__ SX,
                         const float* __restrict__ W, const float* __restrict__ WS,
                         const float* __restrict__ OFF) {
    const int lane = threadIdx.x & 31;
    const int gw = (blockIdx.x * blockDim.x + threadIdx.x) >> 5;
    const int nw = (gridDim.x * blockDim.x) >> 5;

    auto do_x = [&](int t) {
        const int mt  = t & 7;
        const int kt2 = (t >> 3) & 1;
        const int kt  = (t >> 4) & 127;
        const int mb  = t >> 11;
        const int r = mb * BM + mt * 16 + (lane >> 2);
        const int k = kt * 32 + kt2 * 16 + (lane & 3) * 2;
        const float s0 = __ldg(SX + r);
        const float s1 = __ldg(SX + r + 8);
        const float2 x00 = *reinterpret_cast<const float2*>(X + (size_t)r * KK + k);
        const float2 x10 = *reinterpret_cast<const float2*>(X + (size_t)(r + 8) * KK + k);
        const float2 x01 = *reinterpret_cast<const float2*>(X + (size_t)r * KK + k + 8);
        const float2 x11 = *reinterpret_cast<const float2*>(X + (size_t)(r + 8) * KK + k + 8);
        uint4 v;
        v.x = pack2(x00.x * s0, x00.y * s0);
        v.y = pack2(x10.x * s1, x10.y * s1);
        v.z = pack2(x01.x * s0, x01.y * s0);
        v.w = pack2(x11.x * s1, x11.y * s1);
        *reinterpret_cast<uint4*>(g_Xa + (size_t)t * 256 + lane * 8) = v;
    };

    auto do_w = [&](int u) {
        const int nt  = u & 31;
        const int kt2 = (u >> 5) & 1;
        const int kt  = (u >> 6) & 127;
        const int nb  = u >> 13;
        const int n = nb * BN + nt * 8 + (lane >> 2);
        const int k = kt * 32 + kt2 * 16 + (lane & 3) * 2;
        const int g = kt >> 2;
        const float ws  = __ldg(WS + (size_t)n * GG + g);
        const float off = __ldg(OFF + (size_t)n * GG + g);
        const float2 w0 = *reinterpret_cast<const float2*>(W + (size_t)n * KK + k);
        const float2 w1 = *reinterpret_cast<const float2*>(W + (size_t)n * KK + k + 8);
        uint2 v;
        v.x = pack2((w0.x - off) * ws, (w0.y - off) * ws);
        v.y = pack2((w1.x - off) * ws, (w1.y - off) * ws);
        *reinterpret_cast<uint2*>(g_Wb + (size_t)u * 128 + lane * 4) = v;
    };

    const int total = XTILES + WTILES;
    int t = gw * 2;
    const int stride = nw * 2;
    for (; t + 1 < total; t += stride) {
        if (t < XTILES) do_x(t); else do_w(t - XTILES);
        if (t + 1 < XTILES) do_x(t + 1); else do_w(t + 1 - XTILES);
    }
    if (t < total) {
        if (t < XTILES) do_x(t); else do_w(t - XTILES);
    }
}

// ---------------- persistent GEMM: BK=128 two-stage, pipeline carried across tiles ----
__global__ __launch_bounds__(THREADS, 1)
void gemm_persist(float* __restrict__ OUT) {
    extern __shared__ char smem[];
    const uint32_t sbase = smem_u32(smem);

    const int tid = threadIdx.x;
    const int wid = tid >> 5;
    const int lane = tid & 31;
    const int wm = wid >> 2;        // 0..1
    const int wn = wid & 3;         // 0..3

    auto tile_coords = [&](int tile, int& mb, int& nb) {
        const int grp = tile / (8 * NB);
        const int rem = tile - grp * (8 * NB);
        mb = grp * 8 + (rem & 7);
        nb = rem >> 3;
    };

    auto load_stage = [&](int buf, const __half* Ag, const __half* Bg, int t) {
        const uint32_t st = sbase + buf * STAGE_BYTES;
        #pragma unroll
        for (int h = 0; h < 4; h++) {
            const char* a = (const char*)(Ag + (size_t)(4 * t + h) * A_HALVES) + tid * 32;
            const uint32_t sa = st + h * A_KT_BYTES + tid * 32;
            #pragma unroll
            for (int j = 0; j < 2; j++) cp16(sa + j * 16, a + j * 16);
            const char* b = (const char*)(Bg + (size_t)(4 * t + h) * B_HALVES) + tid * 64;
            const uint32_t sb2 = st + STAGE_A_BYTES + h * B_KT_BYTES + tid * 64;
            #pragma unroll
            for (int j = 0; j < 4; j++) cp16(sb2 + j * 16, b + j * 16);
        }
        cp_commit();
    };

    float acc[4][8][4];

    auto compute = [&](int buf) {
        const char* stg = smem + buf * STAGE_BYTES;
        #pragma unroll
        for (int h = 0; h < 4; h++) {
            const char* As = stg + h * A_KT_BYTES;
            const char* Bs = stg + STAGE_A_BYTES + h * B_KT_BYTES;
            #pragma unroll
            for (int kt2 = 0; kt2 < 2; kt2++) {
                uint4 af[4];
                #pragma unroll
                for (int mi = 0; mi < 4; mi++) {
                    const int mt = wm * 4 + mi;
                    af[mi] = *reinterpret_cast<const uint4*>(
                        As + (kt2 * 8 + mt) * 512 + lane * 16);
                }
                uint2 bf[8];
                #pragma unroll
                for (int ni = 0; ni < 8; ni++) {
                    const int nt = wn * 8 + ni;
                    bf[ni] = *reinterpret_cast<const uint2*>(
                        Bs + (kt2 * 32 + nt) * 256 + lane * 8);
                }
                #pragma unroll
                for (int mi = 0; mi < 4; mi++)
                    #pragma unroll
                    for (int ni = 0; ni < 8; ni++)
                        mma_f16(acc[mi][ni],
                                reinterpret_cast<const uint32_t*>(&af[mi]),
                                reinterpret_cast<const uint32_t*>(&bf[ni]));
            }
        }
    };

    int tile = blockIdx.x;
    if (tile >= NTILES) return;

    int mb, nb;
    tile_coords(tile, mb, nb);
    const __half* Ag = g_Xa + (size_t)mb * 128 * A_HALVES;
    const __half* Bg = g_Wb + (size_t)nb * 128 * B_HALVES;
    const __half* AgN = Ag;
    const __half* BgN = Bg;
    int mbN = mb, nbN = nb;

    int buf = 0;
    load_stage(buf, Ag, Bg, 0);

    while (true) {
        #pragma unroll
        for (int i = 0; i < 4; i++)
            #pragma unroll
            for (int j = 0; j < 8; j++)
                #pragma unroll
                for (int c = 0; c < 4; c++) acc[i][j][c] = 0.f;

        #pragma unroll 1
        for (int t = 0; t < KP; t++) {
            cp_wait0();              // this thread's copies for current stage landed
            __syncthreads();         // all copies visible; previous compute finished
            if (t + 1 < KP) {
                load_stage(buf ^ 1, Ag, Bg, t + 1);
            } else {
                const int ntile = tile + GRID;
                if (ntile < NTILES) {
                    tile_coords(ntile, mbN, nbN);
                    AgN = g_Xa + (size_t)mbN * 128 * A_HALVES;
                    BgN = g_Wb + (size_t)nbN * 128 * B_HALVES;
                    load_stage(buf ^ 1, AgN, BgN, 0);   // cross-tile prefetch
                }
            }
            compute(buf);
            buf ^= 1;
        }

        // epilogue: overlaps the in-flight cross-tile prefetch
        const int m0 = mb * BM + wm * 64;
        const int n0 = nb * BN + wn * 64;
        #pragma unroll
        for (int mi = 0; mi < 4; mi++) {
            const int row = m0 + mi * 16 + (lane >> 2);
            #pragma unroll
            for (int ni = 0; ni < 8; ni++) {
                const int col = n0 + ni * 8 + (lane & 3) * 2;
                float2 v0, v1;
                v0.x = acc[mi][ni][0]; v0.y = acc[mi][ni][1];
                v1.x = acc[mi][ni][2]; v1.y = acc[mi][ni][3];
                *reinterpret_cast<float2*>(OUT + (size_t)row * NN + col)       = v0;
                *reinterpret_cast<float2*>(OUT + (size_t)(row + 8) * NN + col) = v1;
            }
        }

        tile += GRID;
        if (tile >= NTILES) break;
        mb = mbN; nb = nbN; Ag = AgN; Bg = BgN;
    }
}

// ---------------- launch ----------------
extern "C" void kernel_launch(void* const* d_in, const int* in_sizes, int n_in,
                              void* d_out, int out_size) {
    const float* X   = (const float*)d_in[0];
    const float* SX  = (const float*)d_in[1];
    const float* W   = (const float*)d_in[2];
    const float* WS  = (const float*)d_in[3];
    const float* OFF = (const float*)d_in[4];
    float* OUT = (float*)d_out;

    cudaFuncSetAttribute(gemm_persist,
                         cudaFuncAttributeMaxDynamicSharedMemorySize, SMEM_TOTAL);

    prep_all<<<2048, 256>>>(X, SX, W, WS, OFF);

    gemm_persist<<<GRID, THREADS, SMEM_TOTAL>>>(OUT);
}

// round 12
// speedup vs baseline: 2.2174x; 1.1923x over previous
#include <cuda_runtime.h>
#include <cuda_fp16.h>
#include <cstdint>
#include <cstddef>

// ---- problem shapes ----
#define MM 8192
#define NN 11008
#define KK 4096
#define GG 32

// ---- GEMM tiling: 128x256 CTA, 16 warps of 64x32, BK=128 two-stage, persistent ----
#define BM 128
#define BN 256
#define KP 32                       // 32 stages of BK=128
#define THREADS 512

#define NB (NN / BN)                // 43
#define MB (MM / BM)                // 64
#define NTILES (MB * NB)            // 2752
#define GRID 148

#define A_HALVES 4096               // per (mb,kt32): 8 KB
#define A_KT_BYTES (A_HALVES * 2)
#define B_HALVES 8192               // per (nb,kt32): 16 KB
#define B_KT_BYTES (B_HALVES * 2)

#define STAGE_A_BYTES (4 * A_KT_BYTES)                 // 32768
#define STAGE_BYTES   (STAGE_A_BYTES + 4 * B_KT_BYTES) // 98304
#define SMEM_TOTAL    (2 * STAGE_BYTES)                // 196608

#define XTILES (MB * 128 * 2 * 8)   // 131072
#define WTILES (NB * 128 * 2 * 32)  // 352256

// ---- scratch ----
__device__ __align__(256) __half g_Xa[(size_t)MM * KK];
__device__ __align__(256) __half g_Wb[(size_t)NN * KK];

// ---------------- helpers ----------------
__device__ __forceinline__ void cp16(uint32_t s, const void* g) {
    asm volatile("cp.async.cg.shared.global [%0], [%1], 16;" :: "r"(s), "l"(g));
}
__device__ __forceinline__ uint32_t smem_u32(const void* p) {
    uint32_t a;
    asm("{ .reg .u64 t; cvta.to.shared.u64 t, %1; cvt.u32.u64 %0, t; }"
        : "=r"(a) : "l"(p));
    return a;
}
__device__ __forceinline__ void cp_commit() {
    asm volatile("cp.async.commit_group;" ::: "memory");
}
__device__ __forceinline__ void cp_wait0() {
    asm volatile("cp.async.wait_group 0;" ::: "memory");
}
__device__ __forceinline__ void mma_f16(float* c, const uint32_t* a, const uint32_t* b) {
    asm volatile(
        "mma.sync.aligned.m16n8k16.row.col.f32.f16.f16.f32 "
        "{%0,%1,%2,%3}, {%4,%5,%6,%7}, {%8,%9}, {%0,%1,%2,%3};\n"
        : "+f"(c[0]), "+f"(c[1]), "+f"(c[2]), "+f"(c[3])
        : "r"(a[0]), "r"(a[1]), "r"(a[2]), "r"(a[3]),
          "r"(b[0]), "r"(b[1]));
}
__device__ __forceinline__ uint32_t pack2(float x, float y) {
    __half2 h = __floats2half2_rn(x, y);
    return *reinterpret_cast<uint32_t*>(&h);
}

// ---------------- merged prepass (X tiles, then W tiles; unroll-2) ----------------
__global__ void prep_all(const float* __restrict__ X, const float* __restrict__ SX,
                         const float* __restrict__ W, const float* __restrict__ WS,
                         const float* __restrict__ OFF) {
    const int lane = threadIdx.x & 31;
    const int gw = (blockIdx.x * blockDim.x + threadIdx.x) >> 5;
    const int nw = (gridDim.x * blockDim.x) >> 5;

    auto do_x = [&](int t) {
        const int mt  = t & 7;
        const int kt2 = (t >> 3) & 1;
        const int kt  = (t >> 4) & 127;
        const int mb  = t >> 11;
        const int r = mb * BM + mt * 16 + (lane >> 2);
        const int k = kt * 32 + kt2 * 16 + (lane & 3) * 2;
        const float s0 = __ldg(SX + r);
        const float s1 = __ldg(SX + r + 8);
        const float2 x00 = *reinterpret_cast<const float2*>(X + (size_t)r * KK + k);
        const float2 x10 = *reinterpret_cast<const float2*>(X + (size_t)(r + 8) * KK + k);
        const float2 x01 = *reinterpret_cast<const float2*>(X + (size_t)r * KK + k + 8);
        const float2 x11 = *reinterpret_cast<const float2*>(X + (size_t)(r + 8) * KK + k + 8);
        uint4 v;
        v.x = pack2(x00.x * s0, x00.y * s0);
        v.y = pack2(x10.x * s1, x10.y * s1);
        v.z = pack2(x01.x * s0, x01.y * s0);
        v.w = pack2(x11.x * s1, x11.y * s1);
        *reinterpret_cast<uint4*>(g_Xa + (size_t)t * 256 + lane * 8) = v;
    };

    auto do_w = [&](int u) {
        const int nt  = u & 31;
        const int kt2 = (u >> 5) & 1;
        const int kt  = (u >> 6) & 127;
        const int nb  = u >> 13;
        const int n = nb * BN + nt * 8 + (lane >> 2);
        const int k = kt * 32 + kt2 * 16 + (lane & 3) * 2;
        const int g = kt >> 2;
        const float ws  = __ldg(WS + (size_t)n * GG + g);
        const float off = __ldg(OFF + (size_t)n * GG + g);
        const float2 w0 = *reinterpret_cast<const float2*>(W + (size_t)n * KK + k);
        const float2 w1 = *reinterpret_cast<const float2*>(W + (size_t)n * KK + k + 8);
        uint2 v;
        v.x = pack2((w0.x - off) * ws, (w0.y - off) * ws);
        v.y = pack2((w1.x - off) * ws, (w1.y - off) * ws);
        *reinterpret_cast<uint2*>(g_Wb + (size_t)u * 128 + lane * 4) = v;
    };

    const int total = XTILES + WTILES;
    int t = gw * 2;
    const int stride = nw * 2;
    for (; t + 1 < total; t += stride) {
        if (t < XTILES) do_x(t); else do_w(t - XTILES);
        if (t + 1 < XTILES) do_x(t + 1); else do_w(t + 1 - XTILES);
    }
    if (t < total) {
        if (t < XTILES) do_x(t); else do_w(t - XTILES);
    }
}

// ---------------- persistent GEMM: 16 warps of 64x32 ----------------
__global__ __launch_bounds__(THREADS, 1)
void gemm_persist(float* __restrict__ OUT) {
    extern __shared__ char smem[];
    const uint32_t sbase = smem_u32(smem);

    const int tid = threadIdx.x;
    const int wid = tid >> 5;       // 0..15
    const int lane = tid & 31;
    const int wm = wid >> 3;        // 0..1  (m half)
    const int wn = wid & 7;         // 0..7  (n eighth)

    auto tile_coords = [&](int tile, int& mb, int& nb) {
        const int grp = tile / (8 * NB);
        const int rem = tile - grp * (8 * NB);
        mb = grp * 8 + (rem & 7);
        nb = rem >> 3;
    };

    auto load_stage = [&](int buf, const __half* Ag, const __half* Bg, int t) {
        const uint32_t st = sbase + buf * STAGE_BYTES;
        #pragma unroll
        for (int h = 0; h < 4; h++) {
            const char* a = (const char*)(Ag + (size_t)(4 * t + h) * A_HALVES) + tid * 16;
            cp16(st + h * A_KT_BYTES + tid * 16, a);
            const char* b = (const char*)(Bg + (size_t)(4 * t + h) * B_HALVES) + tid * 32;
            const uint32_t sb2 = st + STAGE_A_BYTES + h * B_KT_BYTES + tid * 32;
            cp16(sb2, b);
            cp16(sb2 + 16, b + 16);
        }
        cp_commit();
    };

    float acc[4][4][4];

    auto compute = [&](int buf) {
        const char* stg = smem + buf * STAGE_BYTES;
        #pragma unroll
        for (int h = 0; h < 4; h++) {
            const char* As = stg + h * A_KT_BYTES;
            const char* Bs = stg + STAGE_A_BYTES + h * B_KT_BYTES;
            #pragma unroll
            for (int kt2 = 0; kt2 < 2; kt2++) {
                uint4 af[4];
                #pragma unroll
                for (int mi = 0; mi < 4; mi++) {
                    const int mt = wm * 4 + mi;
                    af[mi] = *reinterpret_cast<const uint4*>(
                        As + (kt2 * 8 + mt) * 512 + lane * 16);
                }
                uint2 bf[4];
                #pragma unroll
                for (int ni = 0; ni < 4; ni++) {
                    const int nt = wn * 4 + ni;
                    bf[ni] = *reinterpret_cast<const uint2*>(
                        Bs + (kt2 * 32 + nt) * 256 + lane * 8);
                }
                #pragma unroll
                for (int mi = 0; mi < 4; mi++)
                    #pragma unroll
                    for (int ni = 0; ni < 4; ni++)
                        mma_f16(acc[mi][ni],
                                reinterpret_cast<const uint32_t*>(&af[mi]),
                                reinterpret_cast<const uint32_t*>(&bf[ni]));
            }
        }
    };

    int tile = blockIdx.x;
    if (tile >= NTILES) return;

    int mb, nb;
    tile_coords(tile, mb, nb);
    const __half* Ag = g_Xa + (size_t)mb * 128 * A_HALVES;
    const __half* Bg = g_Wb + (size_t)nb * 128 * B_HALVES;
    const __half* AgN = Ag;
    const __half* BgN = Bg;
    int mbN = mb, nbN = nb;

    int buf = 0;
    load_stage(buf, Ag, Bg, 0);

    while (true) {
        #pragma unroll
        for (int i = 0; i < 4; i++)
            #pragma unroll
            for (int j = 0; j < 4; j++)
                #pragma unroll
                for (int c = 0; c < 4; c++) acc[i][j][c] = 0.f;

        #pragma unroll 1
        for (int t = 0; t < KP; t++) {
            cp_wait0();              // copies for current stage landed
            __syncthreads();         // all visible; previous compute done
            if (t + 1 < KP) {
                load_stage(buf ^ 1, Ag, Bg, t + 1);
            } else {
                const int ntile = tile + GRID;
                if (ntile < NTILES) {
                    tile_coords(ntile, mbN, nbN);
                    AgN = g_Xa + (size_t)mbN * 128 * A_HALVES;
                    BgN = g_Wb + (size_t)nbN * 128 * B_HALVES;
                    load_stage(buf ^ 1, AgN, BgN, 0);   // cross-tile prefetch
                }
            }
            compute(buf);
            buf ^= 1;
        }

        // epilogue: overlaps in-flight cross-tile prefetch
        const int m0 = mb * BM + wm * 64;
        const int n0 = nb * BN + wn * 32;
        #pragma unroll
        for (int mi = 0; mi < 4; mi++) {
            const int row = m0 + mi * 16 + (lane >> 2);
            #pragma unroll
            for (int ni = 0; ni < 4; ni++) {
                const int col = n0 + ni * 8 + (lane & 3) * 2;
                float2 v0, v1;
                v0.x = acc[mi][ni][0]; v0.y = acc[mi][ni][1];
                v1.x = acc[mi][ni][2]; v1.y = acc[mi][ni][3];
                *reinterpret_cast<float2*>(OUT + (size_t)row * NN + col)       = v0;
                *reinterpret_cast<float2*>(OUT + (size_t)(row + 8) * NN + col) = v1;
            }
        }

        tile += GRID;
        if (tile >= NTILES) break;
        mb = mbN; nb = nbN; Ag = AgN; Bg = BgN;
    }
}

// ---------------- launch ----------------
extern "C" void kernel_launch(void* const* d_in, const int* in_sizes, int n_in,
                              void* d_out, int out_size) {
    const float* X   = (const float*)d_in[0];
    const float* SX  = (const float*)d_in[1];
    const float* W   = (const float*)d_in[2];
    const float* WS  = (const float*)d_in[3];
    const float* OFF = (const float*)d_in[4];
    float* OUT = (float*)d_out;

    cudaFuncSetAttribute(gemm_persist,
                         cudaFuncAttributeMaxDynamicSharedMemorySize, SMEM_TOTAL);

    prep_all<<<2048, 256>>>(X, SX, W, WS, OFF);

    gemm_persist<<<GRID, THREADS, SMEM_TOTAL>>>(OUT);
}